// round 3
// baseline (speedup 1.0000x reference)
#include <cuda_runtime.h>
#include <cstdint>

#define MQ   32000
#define HN   32
#define CC   64
#define KK   15
#define COUTN 120

typedef unsigned long long ull;

// scratch
__device__ float  g_mod[(size_t)MQ * COUTN];   // sigmoid(mod), (M,120)
__device__ float4 g_pts4[MQ];                   // padded s_pts

// ---------------- f32x2 packed helpers (FFMA2 etc., sm_103a) ----------------
__device__ __forceinline__ ull pack2(float a, float b) {
    ull r; asm("mov.b64 %0,{%1,%2};" : "=l"(r) : "f"(a), "f"(b)); return r;
}
__device__ __forceinline__ void unpack2(ull v, float& a, float& b) {
    asm("mov.b64 {%0,%1},%2;" : "=f"(a), "=f"(b) : "l"(v));
}
__device__ __forceinline__ ull fma2(ull a, ull b, ull c) {
    ull d; asm("fma.rn.f32x2 %0,%1,%2,%3;" : "=l"(d) : "l"(a), "l"(b), "l"(c)); return d;
}
__device__ __forceinline__ ull mul2(ull a, ull b) {
    ull d; asm("mul.rn.f32x2 %0,%1,%2;" : "=l"(d) : "l"(a), "l"(b)); return d;
}
__device__ __forceinline__ ull add2(ull a, ull b) {
    ull d; asm("add.rn.f32x2 %0,%1,%2;" : "=l"(d) : "l"(a), "l"(b)); return d;
}

// ---------------------------------------------------------------------------
// s_pts -> float4 repack (runs on side stream, overlapped with mlp chunk 0)
// ---------------------------------------------------------------------------
__global__ __launch_bounds__(128) void repack_kernel(const float* __restrict__ s_pts)
{
    __shared__ float st[384];
    const int tid = threadIdx.x;
    const int base = blockIdx.x * 128;
    for (int i = tid; i < 384; i += 128) st[i] = s_pts[base * 3 + i];
    __syncthreads();
    float4 v;
    v.x = st[tid*3+0]; v.y = st[tid*3+1]; v.z = st[tid*3+2]; v.w = 0.f;
    g_pts4[base + tid] = v;
}

// ---------------------------------------------------------------------------
// Kernel 1: per-point MLP with packed f32x2 FMAs.
// Accumulation packed over c-parity; weights pre-interleaved in shared:
//   w1t[c2*64 + j]  = (w1[2c2][j],   w1[2c2+1][j])
//   w2p[j2*120 + o] = (w2[2j2][o],   w2[2j2+1][o])
// smem (ull): w1t 2048 + w2p 3840 + b1 32 + hs2 8192 = 14112 (112896 B)
// ---------------------------------------------------------------------------
__global__ __launch_bounds__(256) void mlp_kernel(
    const float* __restrict__ X,
    const float* __restrict__ w1,
    const float* __restrict__ b1,
    const float* __restrict__ w2,
    int blockBase)
{
    extern __shared__ ull shu[];
    ull* w1t = shu;              // 2048
    ull* w2p = shu + 2048;       // 3840
    ull* b1u = shu + 5888;       // 32
    ull* hs2 = shu + 5920;       // 32*256

    const int tid = threadIdx.x;
    const int r = (blockBase + blockIdx.x) * 256 + tid;

    // build interleaved weight layouts (coalesced global reads)
    for (int i = tid; i < 2048; i += 256) {
        int c2 = i >> 6, j = i & 63;
        w1t[i] = pack2(w1[(2*c2)*64 + j], w1[(2*c2+1)*64 + j]);
    }
    for (int i = tid; i < 3840; i += 256) {
        int j2 = i / 120, o = i - j2 * 120;
        w2p[i] = pack2(w2[(2*j2)*120 + o], w2[(2*j2+1)*120 + o]);
    }
    if (tid < 32) b1u[tid] = ((const ull*)b1)[tid];
    __syncthreads();

    // X row -> packed registers (32 x f32x2)
    ull xr[32];
    {
        const ulonglong2* xv = reinterpret_cast<const ulonglong2*>(X + (size_t)r * 64);
#pragma unroll
        for (int i = 0; i < 16; i++) { ulonglong2 v = xv[i]; xr[2*i] = v.x; xr[2*i+1] = v.y; }
    }
    const float* b1f = reinterpret_cast<const float*>(b1u);

    // hidden layer: 4 outputs per pass
    for (int j = 0; j < 64; j += 4) {
        ull a0 = 0, a1 = 0, a2 = 0, a3 = 0;
#pragma unroll
        for (int c2 = 0; c2 < 32; c2++) {
            ulonglong2 wA = *reinterpret_cast<const ulonglong2*>(&w1t[c2*64 + j]);
            ulonglong2 wB = *reinterpret_cast<const ulonglong2*>(&w1t[c2*64 + j + 2]);
            ull x = xr[c2];
            a0 = fma2(x, wA.x, a0);
            a1 = fma2(x, wA.y, a1);
            a2 = fma2(x, wB.x, a2);
            a3 = fma2(x, wB.y, a3);
        }
        float h[4]; ull aa[4] = {a0, a1, a2, a3};
#pragma unroll
        for (int t = 0; t < 4; t++) {
            float lo, hi; unpack2(aa[t], lo, hi);
            float v = lo + hi + b1f[j + t];
            h[t] = (v >= 0.f) ? v : 0.1f * v;
        }
        hs2[(j >> 1) * 256 + tid]       = pack2(h[0], h[1]);
        hs2[((j >> 1) + 1) * 256 + tid] = pack2(h[2], h[3]);
    }

    // reload hidden packed over j-parity (own data, no sync)
    ull hr[32];
#pragma unroll
    for (int j2 = 0; j2 < 32; j2++) hr[j2] = hs2[j2 * 256 + tid];

    // output layer: mod = sigmoid(h @ W2)
    float* op = g_mod + (size_t)r * COUTN;
    for (int o = 0; o < 120; o += 4) {
        ull a0 = 0, a1 = 0, a2 = 0, a3 = 0;
#pragma unroll
        for (int j2 = 0; j2 < 32; j2++) {
            ulonglong2 wA = *reinterpret_cast<const ulonglong2*>(&w2p[j2*120 + o]);
            ulonglong2 wB = *reinterpret_cast<const ulonglong2*>(&w2p[j2*120 + o + 2]);
            ull h = hr[j2];
            a0 = fma2(h, wA.x, a0);
            a1 = fma2(h, wA.y, a1);
            a2 = fma2(h, wB.x, a2);
            a3 = fma2(h, wB.y, a3);
        }
        ull aa[4] = {a0, a1, a2, a3};
        float4 v; float* vp = &v.x;
#pragma unroll
        for (int t = 0; t < 4; t++) {
            float lo, hi; unpack2(aa[t], lo, hi);
            float s = lo + hi;
            vp[t] = 1.f / (1.f + __expf(-s));
        }
        *reinterpret_cast<float4*>(op + o) = v;
    }
}

// ---------------------------------------------------------------------------
// Kernel 2: warp-per-query geometry + gather-weighted reduction (f32x2 math).
// ---------------------------------------------------------------------------
__global__ __launch_bounds__(256) void kp_kernel(
    const float* __restrict__ q_pts,
    const float* __restrict__ s_feats,
    const int*   __restrict__ nidx,
    const float* __restrict__ kpts,
    const float* __restrict__ Wg,
    float* __restrict__ out,
    int qBase)
{
    __shared__ float sW[15 * 72];    // padded stride 72
    __shared__ float skp[45];
    __shared__ float smod[8][120];

    const int tid  = threadIdx.x;
    const int wid  = tid >> 5;
    const int lane = tid & 31;
    const int m    = qBase + blockIdx.x * 8 + wid;
    const unsigned FULL = 0xffffffffu;

    for (int i = tid; i < 960; i += 256) sW[(i >> 6) * 72 + (i & 63)] = Wg[i];
    if (tid < 45) skp[tid] = kpts[tid];
    for (int i = lane; i < 120; i += 32) smod[wid][i] = g_mod[(size_t)m * 120 + i];
    __syncthreads();

    // geometry: one neighbor per lane
    const int ind = nidx[m * HN + lane];
    const float qx = q_pts[m*3+0], qy = q_pts[m*3+1], qz = q_pts[m*3+2];
    float4 p = g_pts4[ind];
    const float nx = p.x - qx, ny = p.y - qy, nz = p.z - qz;
    float best = 3.4e38f; int bk = 0;
#pragma unroll
    for (int k = 0; k < 15; k++) {
        float dx = nx - skp[k*3+0];
        float dy = ny - skp[k*3+1];
        float dz = nz - skp[k*3+2];
        float d2 = fmaf(dx, dx, fmaf(dy, dy, dz*dz));
        if (d2 < best) { best = d2; bk = k; }   // strict <: first-min like argmin
    }
    const float infl = fmaxf(0.f, 1.f - sqrtf(best));
    const int pk = (bk << 26) | (ind << 6);

    // accumulation: half-warp g handles neighbors 2t+g; lane owns 4 channels
    const int g  = lane >> 4;
    const int cl = (lane & 15) << 2;
    ull acc0 = 0, acc1 = 0;
#pragma unroll
    for (int t = 0; t < 16; t++) {
        const int   h   = 2 * t + g;
        const int   pkh = __shfl_sync(FULL, pk,   h);
        const float s   = __shfl_sync(FULL, infl, h);
        const int   k   = pkh >> 26;
        const int   row = pkh & 0x03FFFFFF;
        const ulonglong2 f = *reinterpret_cast<const ulonglong2*>(s_feats + row + cl);
        const ulonglong2 w = *reinterpret_cast<const ulonglong2*>(&sW[k * 72 + cl]);
        const float sc = smod[wid][(k << 3) + (cl >> 3)] * s;
        const ull scp = pack2(sc, sc);
        acc0 = fma2(f.x, mul2(w.x, scp), acc0);
        acc1 = fma2(f.y, mul2(w.y, scp), acc1);
    }
    // combine even/odd-neighbor halves (lanes L and L+16 own same channels)
    acc0 = add2(acc0, __shfl_xor_sync(FULL, acc0, 16));
    acc1 = add2(acc1, __shfl_xor_sync(FULL, acc1, 16));
    if (g == 0) {
        ulonglong2 v; v.x = acc0; v.y = acc1;
        *reinterpret_cast<ulonglong2*>(out + (size_t)m * 64 + cl) = v;
    }
}

// ---------------------------------------------------------------------------
extern "C" void kernel_launch(void* const* d_in, const int* in_sizes, int n_in,
                              void* d_out, int out_size)
{
    const float* q_pts   = (const float*)d_in[0];
    const float* s_pts   = (const float*)d_in[1];
    const float* s_feats = (const float*)d_in[2];
    const int*   nidx    = (const int*)  d_in[3];
    const float* kpts    = (const float*)d_in[4];
    const float* W       = (const float*)d_in[5];
    const float* w1      = (const float*)d_in[6];
    const float* b1      = (const float*)d_in[7];
    const float* w2      = (const float*)d_in[8];
    float* out = (float*)d_out;

    static cudaStream_t s2 = nullptr;
    static cudaEvent_t ev0, evm[4], evj;
    if (!s2) {
        cudaStreamCreateWithFlags(&s2, cudaStreamNonBlocking);
        cudaEventCreateWithFlags(&ev0, cudaEventDisableTiming);
        for (int i = 0; i < 4; i++) cudaEventCreateWithFlags(&evm[i], cudaEventDisableTiming);
        cudaEventCreateWithFlags(&evj, cudaEventDisableTiming);
        cudaFuncSetAttribute(mlp_kernel, cudaFuncAttributeMaxDynamicSharedMemorySize, 14112 * 8);
    }
    const int smem = 14112 * 8;  // 112896 B

    // fork side stream: s_pts repack runs concurrently with mlp chunk 0
    cudaEventRecord(ev0, 0);
    cudaStreamWaitEvent(s2, ev0, 0);
    repack_kernel<<<250, 128, 0, s2>>>(s_pts);

    static const int mlpBlk[4]  = {32, 32, 32, 29};
    static const int mlpBase[4] = {0, 32, 64, 96};
    static const int kpBlk[4]   = {1024, 1024, 1024, 928};
    static const int kpBase[4]  = {0, 8192, 16384, 24576};

    for (int c = 0; c < 4; c++) {
        mlp_kernel<<<mlpBlk[c], 256, smem>>>(s_feats, w1, b1, w2, mlpBase[c]);
        cudaEventRecord(evm[c], 0);
    }
    for (int c = 0; c < 4; c++) {
        cudaStreamWaitEvent(s2, evm[c], 0);
        kp_kernel<<<kpBlk[c], 256, 0, s2>>>(q_pts, s_feats, nidx, kpts, W, out, kpBase[c]);
    }
    cudaEventRecord(evj, s2);
    cudaStreamWaitEvent(0, evj, 0);
}

// round 4
// speedup vs baseline: 2.4713x; 2.4713x over previous
#include <cuda_runtime.h>
#include <cstdint>

#define MQ   32000
#define HN   32
#define CC   64
#define KK   15
#define COUTN 120

typedef unsigned long long ull;

// scratch
__device__ float  g_mod[(size_t)MQ * COUTN];   // sigmoid(mod), (M,120)
__device__ float4 g_pts4[MQ];                   // padded s_pts

// ---------------- f32x2 packed helpers (sm_103a) ----------------
__device__ __forceinline__ ull pack2(float a, float b) {
    ull r; asm("mov.b64 %0,{%1,%2};" : "=l"(r) : "f"(a), "f"(b)); return r;
}
__device__ __forceinline__ void unpack2(ull v, float& a, float& b) {
    asm("mov.b64 {%0,%1},%2;" : "=f"(a), "=f"(b) : "l"(v));
}
__device__ __forceinline__ ull fma2(ull a, ull b, ull c) {
    ull d; asm("fma.rn.f32x2 %0,%1,%2,%3;" : "=l"(d) : "l"(a), "l"(b), "l"(c)); return d;
}
__device__ __forceinline__ ull mul2(ull a, ull b) {
    ull d; asm("mul.rn.f32x2 %0,%1,%2;" : "=l"(d) : "l"(a), "l"(b)); return d;
}
__device__ __forceinline__ ull add2(ull a, ull b) {
    ull d; asm("add.rn.f32x2 %0,%1,%2;" : "=l"(d) : "l"(a), "l"(b)); return d;
}

// ---------------------------------------------------------------------------
// s_pts -> float4 repack
// ---------------------------------------------------------------------------
__global__ __launch_bounds__(128) void repack_kernel(const float* __restrict__ s_pts)
{
    __shared__ float st[384];
    const int tid = threadIdx.x;
    const int base = blockIdx.x * 128;
    for (int i = tid; i < 384; i += 128) st[i] = s_pts[base * 3 + i];
    __syncthreads();
    float4 v;
    v.x = st[tid*3+0]; v.y = st[tid*3+1]; v.z = st[tid*3+2]; v.w = 0.f;
    g_pts4[base + tid] = v;
}

// ---------------------------------------------------------------------------
// Kernel 1: per-point MLP, f32x2 FMAs, TWO threads per row (halves = warps).
// 256 threads/block -> 128 rows/block, 250 blocks (2000 warps total).
// Warp 2w handles half 0 (hidden j in [0,32), outputs o in [0,60)) of rows
// [w*32, w*32+32); warp 2w+1 handles half 1. All weight LDS warp-uniform.
// smem (ull): w1t 2048 + w2p 3840 + b1 32 + hx 128*33 = 10144 (81152 B)
// ---------------------------------------------------------------------------
__global__ __launch_bounds__(256, 2) void mlp_kernel(
    const float* __restrict__ X,
    const float* __restrict__ w1,
    const float* __restrict__ b1,
    const float* __restrict__ w2)
{
    extern __shared__ ull shu[];
    ull* w1t = shu;              // [c2*64 + j]  = (w1[2c2][j],  w1[2c2+1][j])
    ull* w2p = shu + 2048;       // [j2*120 + o] = (w2[2j2][o],  w2[2j2+1][o])
    ull* b1u = shu + 5888;       // 32
    ull* hx  = shu + 5920;       // 128 rows * stride 33

    const int tid  = threadIdx.x;
    const int wid  = tid >> 5;
    const int lane = tid & 31;
    const int half = wid & 1;
    const int rloc = (wid >> 1) * 32 + lane;        // 0..127
    const int r    = blockIdx.x * 128 + rloc;

    // build interleaved weight layouts
    for (int i = tid; i < 2048; i += 256) {
        int c2 = i >> 6, j = i & 63;
        w1t[i] = pack2(w1[(2*c2)*64 + j], w1[(2*c2+1)*64 + j]);
    }
    for (int i = tid; i < 3840; i += 256) {
        int j2 = i / 120, o = i - j2 * 120;
        w2p[i] = pack2(w2[(2*j2)*120 + o], w2[(2*j2+1)*120 + o]);
    }
    if (tid < 32) b1u[tid] = ((const ull*)b1)[tid];
    __syncthreads();

    const float* b1f = reinterpret_cast<const float*>(b1u);

    // X row -> packed registers (32 x f32x2)
    ull xr[32];
    {
        const ulonglong2* xv = reinterpret_cast<const ulonglong2*>(X + (size_t)r * 64);
#pragma unroll
        for (int i = 0; i < 16; i++) { ulonglong2 v = xv[i]; xr[2*i] = v.x; xr[2*i+1] = v.y; }
    }

    // layer 1: this warp computes h[j] for j in [half*32, half*32+32)
    const int jbase = half * 32;
    for (int jj = 0; jj < 32; jj += 4) {
        const int j = jbase + jj;
        ull a0 = 0, a1 = 0, a2 = 0, a3 = 0;
#pragma unroll
        for (int c2 = 0; c2 < 32; c2++) {
            ulonglong2 wA = *reinterpret_cast<const ulonglong2*>(&w1t[c2*64 + j]);
            ulonglong2 wB = *reinterpret_cast<const ulonglong2*>(&w1t[c2*64 + j + 2]);
            ull x = xr[c2];
            a0 = fma2(x, wA.x, a0);
            a1 = fma2(x, wA.y, a1);
            a2 = fma2(x, wB.x, a2);
            a3 = fma2(x, wB.y, a3);
        }
        float h[4]; ull aa[4] = {a0, a1, a2, a3};
#pragma unroll
        for (int t = 0; t < 4; t++) {
            float lo, hi; unpack2(aa[t], lo, hi);
            float v = lo + hi + b1f[j + t];
            h[t] = (v >= 0.f) ? v : 0.1f * v;
        }
        hx[rloc * 33 + (j >> 1)]     = pack2(h[0], h[1]);
        hx[rloc * 33 + (j >> 1) + 1] = pack2(h[2], h[3]);
    }
    __syncthreads();

    // full hidden vector for this row (j-parity packed)
    ull hr[32];
#pragma unroll
    for (int j2 = 0; j2 < 32; j2++) hr[j2] = hx[rloc * 33 + j2];

    // layer 2: this warp computes o in [half*60, half*60+60)
    float* op = g_mod + (size_t)r * COUTN;
    const int obase = half * 60;
    for (int oo = 0; oo < 60; oo += 4) {
        const int o = obase + oo;
        ull a0 = 0, a1 = 0, a2 = 0, a3 = 0;
#pragma unroll
        for (int j2 = 0; j2 < 32; j2++) {
            ulonglong2 wA = *reinterpret_cast<const ulonglong2*>(&w2p[j2*120 + o]);
            ulonglong2 wB = *reinterpret_cast<const ulonglong2*>(&w2p[j2*120 + o + 2]);
            ull h = hr[j2];
            a0 = fma2(h, wA.x, a0);
            a1 = fma2(h, wA.y, a1);
            a2 = fma2(h, wB.x, a2);
            a3 = fma2(h, wB.y, a3);
        }
        ull aa[4] = {a0, a1, a2, a3};
        float4 v; float* vp = &v.x;
#pragma unroll
        for (int t = 0; t < 4; t++) {
            float lo, hi; unpack2(aa[t], lo, hi);
            float s = lo + hi;
            vp[t] = 1.f / (1.f + __expf(-s));
        }
        *reinterpret_cast<float4*>(op + o) = v;
    }
}

// ---------------------------------------------------------------------------
// Kernel 2: warp-per-query geometry + gather-weighted reduction (round-2).
// ---------------------------------------------------------------------------
__global__ __launch_bounds__(256) void kp_kernel(
    const float* __restrict__ q_pts,
    const float* __restrict__ s_feats,
    const int*   __restrict__ nidx,
    const float* __restrict__ kpts,
    const float* __restrict__ Wg,
    float* __restrict__ out)
{
    __shared__ float sW[15 * 72];    // padded stride 72
    __shared__ float skp[45];
    __shared__ float smod[8][120];

    const int tid  = threadIdx.x;
    const int wid  = tid >> 5;
    const int lane = tid & 31;
    const int m    = blockIdx.x * 8 + wid;
    const unsigned FULL = 0xffffffffu;

    for (int i = tid; i < 960; i += 256) sW[(i >> 6) * 72 + (i & 63)] = Wg[i];
    if (tid < 45) skp[tid] = kpts[tid];
    for (int i = lane; i < 120; i += 32) smod[wid][i] = g_mod[(size_t)m * 120 + i];
    __syncthreads();

    // geometry: one neighbor per lane
    const int ind = nidx[m * HN + lane];
    const float qx = q_pts[m*3+0], qy = q_pts[m*3+1], qz = q_pts[m*3+2];
    float4 p = g_pts4[ind];
    const float nx = p.x - qx, ny = p.y - qy, nz = p.z - qz;
    float best = 3.4e38f; int bk = 0;
#pragma unroll
    for (int k = 0; k < 15; k++) {
        float dx = nx - skp[k*3+0];
        float dy = ny - skp[k*3+1];
        float dz = nz - skp[k*3+2];
        float d2 = fmaf(dx, dx, fmaf(dy, dy, dz*dz));
        if (d2 < best) { best = d2; bk = k; }   // strict <: first-min like argmin
    }
    const float infl = fmaxf(0.f, 1.f - sqrtf(best));
    const int pk = (bk << 26) | (ind << 6);

    // accumulation: half-warp g handles neighbors 2t+g; lane owns 4 channels
    const int g  = lane >> 4;
    const int cl = (lane & 15) << 2;
    ull acc0 = 0, acc1 = 0;
#pragma unroll
    for (int t = 0; t < 16; t++) {
        const int   h   = 2 * t + g;
        const int   pkh = __shfl_sync(FULL, pk,   h);
        const float s   = __shfl_sync(FULL, infl, h);
        const int   k   = pkh >> 26;
        const int   row = pkh & 0x03FFFFFF;
        const ulonglong2 f = *reinterpret_cast<const ulonglong2*>(s_feats + row + cl);
        const ulonglong2 w = *reinterpret_cast<const ulonglong2*>(&sW[k * 72 + cl]);
        const float sc = smod[wid][(k << 3) + (cl >> 3)] * s;
        const ull scp = pack2(sc, sc);
        acc0 = fma2(f.x, mul2(w.x, scp), acc0);
        acc1 = fma2(f.y, mul2(w.y, scp), acc1);
    }
    acc0 = add2(acc0, __shfl_xor_sync(FULL, acc0, 16));
    acc1 = add2(acc1, __shfl_xor_sync(FULL, acc1, 16));
    if (g == 0) {
        ulonglong2 v; v.x = acc0; v.y = acc1;
        *reinterpret_cast<ulonglong2*>(out + (size_t)m * 64 + cl) = v;
    }
}

// ---------------------------------------------------------------------------
extern "C" void kernel_launch(void* const* d_in, const int* in_sizes, int n_in,
                              void* d_out, int out_size)
{
    const float* q_pts   = (const float*)d_in[0];
    const float* s_pts   = (const float*)d_in[1];
    const float* s_feats = (const float*)d_in[2];
    const int*   nidx    = (const int*)  d_in[3];
    const float* kpts    = (const float*)d_in[4];
    const float* W       = (const float*)d_in[5];
    const float* w1      = (const float*)d_in[6];
    const float* b1      = (const float*)d_in[7];
    const float* w2      = (const float*)d_in[8];
    float* out = (float*)d_out;

    const int smem = 10144 * 8;  // 81152 B
    static bool init = false;
    if (!init) {
        cudaFuncSetAttribute(mlp_kernel, cudaFuncAttributeMaxDynamicSharedMemorySize, smem);
        init = true;
    }

    repack_kernel<<<250, 128>>>(s_pts);
    mlp_kernel<<<250, 256, smem>>>(s_feats, w1, b1, w2);
    kp_kernel<<<MQ / 8, 256>>>(q_pts, s_feats, nidx, kpts, W, out);
}